// round 11
// baseline (speedup 1.0000x reference)
#include <cuda_runtime.h>
#include <cuda_fp16.h>
#include <cstdint>

// ============================================================================
// out[b,c] = xs[b] + ps[c] - 2 * dot(x_b, p_c)
//   x = 3*l2norm(inputs) [4096,128], p = 3*l2norm(kernel) [16384,128]
// R11: pipelined epilogue. Each warp splits its 64x64 tile into two ni-halves;
//      the first half's epilogue (staged, per-warp, syncwarp-only) overlaps
//      the second half's HMMAs. Dedicated 16KB staging buffer (SMEM 112KB,
//      still 2 CTAs/SM). f16 unit-normalized inputs, f32 accum.
// ============================================================================

static constexpr int B_ROWS = 4096;
static constexpr int C_ROWS = 16384;
static constexpr int D_DIM  = 128;

static constexpr int N_TILES   = C_ROWS / 128;        // 128
static constexpr int M_TILES   = B_ROWS / 128;        // 32
static constexpr int TOT_TILES = N_TILES * M_TILES;   // 4096

static constexpr int GRID = 296;                      // 2 CTAs/SM, one wave
static constexpr int BASE_CHUNK = TOT_TILES / GRID;   // 13
static constexpr int REM_CHUNK  = TOT_TILES % GRID;   // 248

static constexpr int SMEM_A_OFF  = 0;
static constexpr int TILE_BYTES  = 128 * 256;         // 32768 (f16 tile)
static constexpr int SMEM_B0_OFF = TILE_BYTES;        // 32768
static constexpr int SMEM_B1_OFF = 2 * TILE_BYTES;    // 65536
static constexpr int SMEM_STG_OFF = 3 * TILE_BYTES;   // 98304 (16KB staging)
static constexpr int SMEM_TOTAL  = SMEM_STG_OFF + 16384;  // 114688

// ---------------- scratch (no allocation allowed) ----------------
__device__ __half g_x[B_ROWS * D_DIM];   // unit-normalized rows
__device__ __half g_p[C_ROWS * D_DIM];
__device__ float g_xs[B_ROWS];           // ||3*norm(row)||^2
__device__ float g_ps[C_ROWS];

__device__ __forceinline__ uint32_t smem_u32(const void* p) {
    uint32_t a;
    asm("{ .reg .u64 t; cvta.to.shared.u64 t, %1; cvt.u32.u64 %0, t; }" : "=r"(a) : "l"(p));
    return a;
}
__device__ __forceinline__ void cp_async16(uint32_t dst, const void* src) {
    asm volatile("cp.async.cg.shared.global [%0], [%1], 16;" :: "r"(dst), "l"(src));
}
__device__ __forceinline__ void ldmatrix_x4(uint32_t& r0, uint32_t& r1,
                                            uint32_t& r2, uint32_t& r3, uint32_t addr) {
    asm volatile("ldmatrix.sync.aligned.m8n8.x4.shared.b16 {%0,%1,%2,%3}, [%4];"
                 : "=r"(r0), "=r"(r1), "=r"(r2), "=r"(r3) : "r"(addr));
}
__device__ __forceinline__ void mma_f16_f32(float& c0, float& c1, float& c2, float& c3,
                                            uint32_t a0, uint32_t a1, uint32_t a2, uint32_t a3,
                                            uint32_t b0, uint32_t b1) {
    asm volatile(
        "mma.sync.aligned.m16n8k16.row.col.f32.f16.f16.f32 "
        "{%0,%1,%2,%3}, {%4,%5,%6,%7}, {%8,%9}, {%0,%1,%2,%3};"
        : "+f"(c0), "+f"(c1), "+f"(c2), "+f"(c3)
        : "r"(a0), "r"(a1), "r"(a2), "r"(a3), "r"(b0), "r"(b1));
}
__device__ __forceinline__ void sts_v2(uint32_t addr, float x, float y) {
    asm volatile("st.shared.v2.f32 [%0], {%1,%2};" :: "r"(addr), "f"(x), "f"(y));
}
__device__ __forceinline__ void lds_v4(uint32_t addr, float& x, float& y, float& z, float& w) {
    asm volatile("ld.shared.v4.f32 {%0,%1,%2,%3}, [%4];"
                 : "=f"(x), "=f"(y), "=f"(z), "=f"(w) : "r"(addr));
}
__device__ __forceinline__ void stg_cs_v4(float* p, float x, float y, float z, float w) {
    asm volatile("st.global.cs.v4.f32 [%0], {%1,%2,%3,%4};"
                 :: "l"(p), "f"(x), "f"(y), "f"(z), "f"(w) : "memory");
}

// ============================================================================
// Kernel 1: normalize (unit scale) -> f16; xs/ps = 9*sum(u^2).
// 8 lanes per row; each lane holds 4 consecutive float4 (MLP=4/lane).
// ============================================================================
__global__ __launch_bounds__(256)
void normalize_kernel(const float* __restrict__ inp, const float* __restrict__ ker) {
    int gthread = blockIdx.x * blockDim.x + threadIdx.x;
    int row = gthread >> 3;
    int j   = gthread & 7;
    if (row >= B_ROWS + C_ROWS) return;

    const float* src;
    __half* outv;
    float* outs;
    int r;
    if (row < B_ROWS) { src = inp; outv = g_x; outs = g_xs; r = row; }
    else { src = ker; outv = g_p; outs = g_ps; r = row - B_ROWS; }

    const float4* s4 = reinterpret_cast<const float4*>(src + (size_t)r * D_DIM) + j * 4;
    float4 v0 = s4[0];
    float4 v1 = s4[1];
    float4 v2 = s4[2];
    float4 v3 = s4[3];

    float ss = v0.x * v0.x + v0.y * v0.y + v0.z * v0.z + v0.w * v0.w
             + v1.x * v1.x + v1.y * v1.y + v1.z * v1.z + v1.w * v1.w
             + v2.x * v2.x + v2.y * v2.y + v2.z * v2.z + v2.w * v2.w
             + v3.x * v3.x + v3.y * v3.y + v3.z * v3.z + v3.w * v3.w;
    #pragma unroll
    for (int o = 4; o; o >>= 1) ss += __shfl_xor_sync(0xffffffffu, ss, o);

    float rs = rsqrtf(fmaxf(ss, 1e-12f));
    __half2 h0 = __floats2half2_rn(v0.x * rs, v0.y * rs);
    __half2 h1 = __floats2half2_rn(v0.z * rs, v0.w * rs);
    __half2 h2 = __floats2half2_rn(v1.x * rs, v1.y * rs);
    __half2 h3 = __floats2half2_rn(v1.z * rs, v1.w * rs);
    __half2 h4 = __floats2half2_rn(v2.x * rs, v2.y * rs);
    __half2 h5 = __floats2half2_rn(v2.z * rs, v2.w * rs);
    __half2 h6 = __floats2half2_rn(v3.x * rs, v3.y * rs);
    __half2 h7 = __floats2half2_rn(v3.z * rs, v3.w * rs);
    uint4 pka, pkb;
    pka.x = *reinterpret_cast<uint32_t*>(&h0);
    pka.y = *reinterpret_cast<uint32_t*>(&h1);
    pka.z = *reinterpret_cast<uint32_t*>(&h2);
    pka.w = *reinterpret_cast<uint32_t*>(&h3);
    pkb.x = *reinterpret_cast<uint32_t*>(&h4);
    pkb.y = *reinterpret_cast<uint32_t*>(&h5);
    pkb.z = *reinterpret_cast<uint32_t*>(&h6);
    pkb.w = *reinterpret_cast<uint32_t*>(&h7);
    uint4* d4 = reinterpret_cast<uint4*>(outv + (size_t)r * D_DIM) + j * 2;
    d4[0] = pka;
    d4[1] = pkb;

    if (j == 0) outs[r] = 9.0f * ss * rs * rs;
}

// async-load one 128x128 f16 tile (row-major 256B rows) into swizzled smem
__device__ __forceinline__ void load_tile_async(uint32_t smem_dst, const __half* gsrc,
                                                int tid) {
    const char* src = reinterpret_cast<const char*>(gsrc);
    #pragma unroll
    for (int it = 0; it < 16; it++) {
        int i = it * 128 + tid;
        int row = i >> 4, c = i & 15;
        uint32_t doff = row * 256 + ((c ^ (row & 7)) << 4);
        cp_async16(smem_dst + doff, src + (size_t)row * 256 + c * 16);
    }
}

// ============================================================================
// Kernel 2: persistent f16->f32 HMMA GEMM; 4 warps @ 64x64 split into two
// ni-halves with the half-0 epilogue overlapped under half-1 compute.
// SMEM tiles: 256B rows, chunk c of row r at phys (c ^ (r & 7)).
// Staging: per-warp 4KB, 128B rows of 8 chunks, chunk c at phys (c ^ (r & 7)).
// ============================================================================
__global__ __launch_bounds__(128, 2)
void gemm_kernel(float* __restrict__ out) {
    extern __shared__ char smem[];
    const uint32_t sb = smem_u32(smem);

    const int tid  = threadIdx.x;
    const int lane = tid & 31;
    const int wid  = tid >> 5;
    const int warp_m = wid & 1;
    const int warp_n = wid >> 1;

    const int bid = blockIdx.x;
    int g0 = bid * BASE_CHUNK + min(bid, REM_CHUNK);
    int g1 = g0 + BASE_CHUNK + (bid < REM_CHUNK ? 1 : 0);

    // n-major tile order: g -> (m_tile = g>>7, n_tile = g&127)
    load_tile_async(sb + SMEM_A_OFF, g_x + (size_t)((g0 >> 7) << 7) * D_DIM, tid);
    load_tile_async(sb + SMEM_B0_OFF, g_p + (size_t)((g0 & 127) << 7) * D_DIM, tid);
    asm volatile("cp.async.commit_group;");

    const int a_row_base = warp_m * 64 + (lane & 7) + ((lane >> 3) & 1) * 8;
    const int a_kc_lane  = (lane >> 4);
    const int b_row_base = warp_n * 64 + (lane & 7) + (lane >> 4) * 8;
    const int b_kc_lane  = ((lane >> 3) & 1);

    const uint32_t stg = sb + SMEM_STG_OFF + wid * 4096;
    const int row0 = lane >> 2;              // 0..7
    const int sts_sub = ((lane & 3) >> 1);   // chunk sub-index
    const int sts_w8  = (lane & 1) * 8;      // 8B half within chunk

    int cur = 0;
    for (int g = g0; g < g1; g++) {
        asm volatile("cp.async.wait_group 0;" ::: "memory");
        __syncthreads();

        const bool has_next = (g + 1 < g1);
        const int  next_m   = (g + 1) >> 7;

        if (has_next) {
            load_tile_async(sb + (cur ? SMEM_B0_OFF : SMEM_B1_OFF),
                            g_p + (size_t)(((g + 1) & 127) << 7) * D_DIM, tid);
            asm volatile("cp.async.commit_group;");
        }

        const uint32_t sbB = sb + (cur ? SMEM_B1_OFF : SMEM_B0_OFF);
        const int n0 = (g & 127) << 7;
        const int m0 = (g >> 7) << 7;

        // ---- two ni-halves; epilogue of half h overlaps compute of h+1 ----
        #pragma unroll
        for (int h = 0; h < 2; h++) {
            float acc[4][4][4];
            #pragma unroll
            for (int mi = 0; mi < 4; mi++)
                #pragma unroll
                for (int ni = 0; ni < 4; ni++)
                    #pragma unroll
                    for (int k = 0; k < 4; k++) acc[mi][ni][k] = 0.0f;

            #pragma unroll
            for (int ks = 0; ks < 8; ks++) {
                uint32_t a[4][4];
                #pragma unroll
                for (int mi = 0; mi < 4; mi++) {
                    int row = a_row_base + mi * 16;
                    int kc  = ks * 2 + a_kc_lane;
                    uint32_t addr = sb + SMEM_A_OFF + row * 256 + ((kc ^ (row & 7)) << 4);
                    ldmatrix_x4(a[mi][0], a[mi][1], a[mi][2], a[mi][3], addr);
                }
                uint32_t b[4][2];
                #pragma unroll
                for (int gg = 0; gg < 2; gg++) {
                    int row = b_row_base + h * 32 + gg * 16;
                    int kc  = ks * 2 + b_kc_lane;
                    uint32_t addr = sbB + row * 256 + ((kc ^ (row & 7)) << 4);
                    ldmatrix_x4(b[2 * gg][0], b[2 * gg][1], b[2 * gg + 1][0], b[2 * gg + 1][1], addr);
                }
                #pragma unroll
                for (int mi = 0; mi < 4; mi++)
                    #pragma unroll
                    for (int ni = 0; ni < 4; ni++)
                        mma_f16_f32(acc[mi][ni][0], acc[mi][ni][1], acc[mi][ni][2], acc[mi][ni][3],
                                    a[mi][0], a[mi][1], a[mi][2], a[mi][3],
                                    b[ni][0], b[ni][1]);
            }

            // ---- per-warp staged epilogue for this half (32 cols) ----
            const int c_col0 = n0 + warp_n * 64 + h * 32;
            const int c_base = c_col0 + (lane & 3) * 2;
            float2 ps_[4];
            #pragma unroll
            for (int ni = 0; ni < 4; ni++)
                ps_[ni] = *reinterpret_cast<const float2*>(g_ps + c_base + ni * 8);

            #pragma unroll
            for (int mi = 0; mi < 4; mi++) {
                int r_base = m0 + warp_m * 64 + mi * 16;
                float xs0 = g_xs[r_base + row0];
                float xs1 = g_xs[r_base + 8 + row0];

                #pragma unroll
                for (int ni = 0; ni < 4; ni++) {
                    int c16 = ni * 2 + sts_sub;
                    uint32_t a0 = stg + row0 * 128 + ((uint32_t)(c16 ^ (row0 & 7)) << 4) + sts_w8;
                    uint32_t a1 = stg + (row0 + 8) * 128 + ((uint32_t)(c16 ^ (row0 & 7)) << 4) + sts_w8;
                    sts_v2(a0, xs0 + ps_[ni].x - 18.0f * acc[mi][ni][0],
                               xs0 + ps_[ni].y - 18.0f * acc[mi][ni][1]);
                    sts_v2(a1, xs1 + ps_[ni].x - 18.0f * acc[mi][ni][2],
                               xs1 + ps_[ni].y - 18.0f * acc[mi][ni][3]);
                }
                __syncwarp();

                // read physically-linear (conflict-free), decode logical chunk
                #pragma unroll
                for (int i = 0; i < 4; i++) {
                    int pos = i * 512 + lane * 16;       // 2048B region
                    int rl  = pos >> 7;                  // 0..15
                    int cch = (lane & 7) ^ (rl & 7);     // logical 16B chunk
                    float x, y, z, w;
                    lds_v4(stg + pos, x, y, z, w);
                    float* gp = out + (size_t)(r_base + rl) * C_ROWS + c_col0 + cch * 4;
                    stg_cs_v4(gp, x, y, z, w);
                }
                __syncwarp();
            }
        }

        // ---- A reload on m-row crossing ----
        if (has_next && next_m != (g >> 7)) {
            __syncthreads();
            load_tile_async(sb + SMEM_A_OFF, g_x + (size_t)(next_m << 7) * D_DIM, tid);
            asm volatile("cp.async.commit_group;");
        }

        cur ^= 1;
    }
}

// ============================================================================
extern "C" void kernel_launch(void* const* d_in, const int* in_sizes, int n_in,
                              void* d_out, int out_size) {
    (void)in_sizes; (void)n_in; (void)out_size;
    const float* inp = (const float*)d_in[0];   // inputs [4096,128] fp32
    const float* ker = (const float*)d_in[1];   // kernel [16384,128] fp32
    float* out = (float*)d_out;                 // [4096,16384] fp32

    cudaFuncSetAttribute(gemm_kernel, cudaFuncAttributeMaxDynamicSharedMemorySize, SMEM_TOTAL);

    int total_rows = B_ROWS + C_ROWS;            // 8 lanes per row
    int nthreads = total_rows * 8;
    normalize_kernel<<<(nthreads + 255) / 256, 256>>>(inp, ker);

    gemm_kernel<<<GRID, 128, SMEM_TOTAL>>>(out);
}

// round 12
// speedup vs baseline: 1.1126x; 1.1126x over previous
#include <cuda_runtime.h>
#include <cuda_fp16.h>
#include <cstdint>

// ============================================================================
// out[b,c] = xs[b] + ps[c] - 2 * dot(x_b, p_c)
//   x = 3*l2norm(inputs) [4096,128], p = 3*l2norm(kernel) [16384,128]
// R12: consolidation at the measured legacy-mma.sync floor (~246 TF/s).
//      Best structure (R6/R10): 4 warps @ 64x64, 2 CTAs/SM, persistent CTAs,
//      B double-buffer, staged coalesced epilogue, f16 unit-norm + f32 accum.
//      Change: dedicated 16KB staging buffer -> pre-epilogue __syncthreads
//      removed (per-warp epilogue, syncwarp only).
// ============================================================================

static constexpr int B_ROWS = 4096;
static constexpr int C_ROWS = 16384;
static constexpr int D_DIM  = 128;

static constexpr int N_TILES   = C_ROWS / 128;        // 128
static constexpr int M_TILES   = B_ROWS / 128;        // 32
static constexpr int TOT_TILES = N_TILES * M_TILES;   // 4096

static constexpr int GRID = 296;                      // 2 CTAs/SM, one wave
static constexpr int BASE_CHUNK = TOT_TILES / GRID;   // 13
static constexpr int REM_CHUNK  = TOT_TILES % GRID;   // 248

static constexpr int SMEM_A_OFF  = 0;
static constexpr int TILE_BYTES  = 128 * 256;         // 32768 (f16 tile)
static constexpr int SMEM_B0_OFF = TILE_BYTES;        // 32768
static constexpr int SMEM_B1_OFF = 2 * TILE_BYTES;    // 65536
static constexpr int SMEM_STG_OFF = 3 * TILE_BYTES;   // 98304 (16KB staging)
static constexpr int SMEM_TOTAL  = SMEM_STG_OFF + 16384;  // 114688

// ---------------- scratch (no allocation allowed) ----------------
__device__ __half g_x[B_ROWS * D_DIM];   // unit-normalized rows
__device__ __half g_p[C_ROWS * D_DIM];
__device__ float g_xs[B_ROWS];           // ||3*norm(row)||^2
__device__ float g_ps[C_ROWS];

__device__ __forceinline__ uint32_t smem_u32(const void* p) {
    uint32_t a;
    asm("{ .reg .u64 t; cvta.to.shared.u64 t, %1; cvt.u32.u64 %0, t; }" : "=r"(a) : "l"(p));
    return a;
}
__device__ __forceinline__ void cp_async16(uint32_t dst, const void* src) {
    asm volatile("cp.async.cg.shared.global [%0], [%1], 16;" :: "r"(dst), "l"(src));
}
__device__ __forceinline__ void ldmatrix_x4(uint32_t& r0, uint32_t& r1,
                                            uint32_t& r2, uint32_t& r3, uint32_t addr) {
    asm volatile("ldmatrix.sync.aligned.m8n8.x4.shared.b16 {%0,%1,%2,%3}, [%4];"
                 : "=r"(r0), "=r"(r1), "=r"(r2), "=r"(r3) : "r"(addr));
}
__device__ __forceinline__ void mma_f16_f32(float& c0, float& c1, float& c2, float& c3,
                                            uint32_t a0, uint32_t a1, uint32_t a2, uint32_t a3,
                                            uint32_t b0, uint32_t b1) {
    asm volatile(
        "mma.sync.aligned.m16n8k16.row.col.f32.f16.f16.f32 "
        "{%0,%1,%2,%3}, {%4,%5,%6,%7}, {%8,%9}, {%0,%1,%2,%3};"
        : "+f"(c0), "+f"(c1), "+f"(c2), "+f"(c3)
        : "r"(a0), "r"(a1), "r"(a2), "r"(a3), "r"(b0), "r"(b1));
}
__device__ __forceinline__ void sts_v2(uint32_t addr, float x, float y) {
    asm volatile("st.shared.v2.f32 [%0], {%1,%2};" :: "r"(addr), "f"(x), "f"(y));
}
__device__ __forceinline__ void lds_v4(uint32_t addr, float& x, float& y, float& z, float& w) {
    asm volatile("ld.shared.v4.f32 {%0,%1,%2,%3}, [%4];"
                 : "=f"(x), "=f"(y), "=f"(z), "=f"(w) : "r"(addr));
}
__device__ __forceinline__ void stg_cs_v4(float* p, float x, float y, float z, float w) {
    asm volatile("st.global.cs.v4.f32 [%0], {%1,%2,%3,%4};"
                 :: "l"(p), "f"(x), "f"(y), "f"(z), "f"(w) : "memory");
}

// ============================================================================
// Kernel 1: normalize (unit scale) -> f16; xs/ps = 9*sum(u^2).
// 8 lanes per row; each lane holds 4 consecutive float4 (MLP=4/lane).
// ============================================================================
__global__ __launch_bounds__(256)
void normalize_kernel(const float* __restrict__ inp, const float* __restrict__ ker) {
    int gthread = blockIdx.x * blockDim.x + threadIdx.x;
    int row = gthread >> 3;
    int j   = gthread & 7;
    if (row >= B_ROWS + C_ROWS) return;

    const float* src;
    __half* outv;
    float* outs;
    int r;
    if (row < B_ROWS) { src = inp; outv = g_x; outs = g_xs; r = row; }
    else { src = ker; outv = g_p; outs = g_ps; r = row - B_ROWS; }

    const float4* s4 = reinterpret_cast<const float4*>(src + (size_t)r * D_DIM) + j * 4;
    float4 v0 = s4[0];
    float4 v1 = s4[1];
    float4 v2 = s4[2];
    float4 v3 = s4[3];

    float ss = v0.x * v0.x + v0.y * v0.y + v0.z * v0.z + v0.w * v0.w
             + v1.x * v1.x + v1.y * v1.y + v1.z * v1.z + v1.w * v1.w
             + v2.x * v2.x + v2.y * v2.y + v2.z * v2.z + v2.w * v2.w
             + v3.x * v3.x + v3.y * v3.y + v3.z * v3.z + v3.w * v3.w;
    #pragma unroll
    for (int o = 4; o; o >>= 1) ss += __shfl_xor_sync(0xffffffffu, ss, o);

    float rs = rsqrtf(fmaxf(ss, 1e-12f));       // unit scale
    __half2 h0 = __floats2half2_rn(v0.x * rs, v0.y * rs);
    __half2 h1 = __floats2half2_rn(v0.z * rs, v0.w * rs);
    __half2 h2 = __floats2half2_rn(v1.x * rs, v1.y * rs);
    __half2 h3 = __floats2half2_rn(v1.z * rs, v1.w * rs);
    __half2 h4 = __floats2half2_rn(v2.x * rs, v2.y * rs);
    __half2 h5 = __floats2half2_rn(v2.z * rs, v2.w * rs);
    __half2 h6 = __floats2half2_rn(v3.x * rs, v3.y * rs);
    __half2 h7 = __floats2half2_rn(v3.z * rs, v3.w * rs);
    uint4 pka, pkb;
    pka.x = *reinterpret_cast<uint32_t*>(&h0);
    pka.y = *reinterpret_cast<uint32_t*>(&h1);
    pka.z = *reinterpret_cast<uint32_t*>(&h2);
    pka.w = *reinterpret_cast<uint32_t*>(&h3);
    pkb.x = *reinterpret_cast<uint32_t*>(&h4);
    pkb.y = *reinterpret_cast<uint32_t*>(&h5);
    pkb.z = *reinterpret_cast<uint32_t*>(&h6);
    pkb.w = *reinterpret_cast<uint32_t*>(&h7);
    uint4* d4 = reinterpret_cast<uint4*>(outv + (size_t)r * D_DIM) + j * 2;
    d4[0] = pka;
    d4[1] = pkb;

    if (j == 0) outs[r] = 9.0f * ss * rs * rs;  // sum((3u)^2)
}

// async-load one 128x128 f16 tile (row-major 256B rows) into swizzled smem
__device__ __forceinline__ void load_tile_async(uint32_t smem_dst, const __half* gsrc,
                                                int tid) {
    const char* src = reinterpret_cast<const char*>(gsrc);
    #pragma unroll
    for (int it = 0; it < 16; it++) {
        int i = it * 128 + tid;
        int row = i >> 4, c = i & 15;
        uint32_t doff = row * 256 + ((c ^ (row & 7)) << 4);
        cp_async16(smem_dst + doff, src + (size_t)row * 256 + c * 16);
    }
}

// ============================================================================
// Kernel 2: persistent f16->f32 HMMA GEMM; 4 warps @ 64x64; per-warp staged
// epilogue in a dedicated buffer (no CTA barrier between compute & epilogue).
// SMEM tiles: 256B rows = 16 chunks of 16B; chunk c of row r at (c ^ (r&7)).
// ============================================================================
__global__ __launch_bounds__(128, 2)
void gemm_kernel(float* __restrict__ out) {
    extern __shared__ char smem[];
    const uint32_t sb = smem_u32(smem);

    const int tid  = threadIdx.x;
    const int lane = tid & 31;
    const int wid  = tid >> 5;
    const int warp_m = wid & 1;
    const int warp_n = wid >> 1;

    const int bid = blockIdx.x;
    int g0 = bid * BASE_CHUNK + min(bid, REM_CHUNK);
    int g1 = g0 + BASE_CHUNK + (bid < REM_CHUNK ? 1 : 0);

    // n-major tile order: g -> (m_tile = g>>7, n_tile = g&127)
    load_tile_async(sb + SMEM_A_OFF, g_x + (size_t)((g0 >> 7) << 7) * D_DIM, tid);
    load_tile_async(sb + SMEM_B0_OFF, g_p + (size_t)((g0 & 127) << 7) * D_DIM, tid);
    asm volatile("cp.async.commit_group;");

    const int a_row_base = warp_m * 64 + (lane & 7) + ((lane >> 3) & 1) * 8;
    const int a_kc_lane  = (lane >> 4);
    const int b_row_base = warp_n * 64 + (lane & 7) + (lane >> 4) * 8;
    const int b_kc_lane  = ((lane >> 3) & 1);

    const uint32_t stg = sb + SMEM_STG_OFF + wid * 4096;  // dedicated 4KB/warp
    const int row0 = lane >> 2;              // 0..7
    const int ib   = (lane & 3) << 3;

    int cur = 0;
    for (int g = g0; g < g1; g++) {
        asm volatile("cp.async.wait_group 0;" ::: "memory");
        __syncthreads();

        const bool has_next = (g + 1 < g1);
        const int  next_m   = (g + 1) >> 7;

        if (has_next) {
            load_tile_async(sb + (cur ? SMEM_B0_OFF : SMEM_B1_OFF),
                            g_p + (size_t)(((g + 1) & 127) << 7) * D_DIM, tid);
            asm volatile("cp.async.commit_group;");
        }

        // ---- compute 128x128 tile ----
        float acc[4][8][4];
        #pragma unroll
        for (int mi = 0; mi < 4; mi++)
            #pragma unroll
            for (int ni = 0; ni < 8; ni++)
                #pragma unroll
                for (int k = 0; k < 4; k++) acc[mi][ni][k] = 0.0f;

        const uint32_t sbB = sb + (cur ? SMEM_B1_OFF : SMEM_B0_OFF);

        #pragma unroll
        for (int ks = 0; ks < 8; ks++) {
            uint32_t a[4][4];
            #pragma unroll
            for (int mi = 0; mi < 4; mi++) {
                int row = a_row_base + mi * 16;
                int kc  = ks * 2 + a_kc_lane;
                uint32_t addr = sb + SMEM_A_OFF + row * 256 + ((kc ^ (row & 7)) << 4);
                ldmatrix_x4(a[mi][0], a[mi][1], a[mi][2], a[mi][3], addr);
            }
            uint32_t b[8][2];
            #pragma unroll
            for (int gg = 0; gg < 4; gg++) {
                int row = b_row_base + gg * 16;
                int kc  = ks * 2 + b_kc_lane;
                uint32_t addr = sbB + row * 256 + ((kc ^ (row & 7)) << 4);
                ldmatrix_x4(b[2 * gg][0], b[2 * gg][1], b[2 * gg + 1][0], b[2 * gg + 1][1], addr);
            }
            #pragma unroll
            for (int mi = 0; mi < 4; mi++)
                #pragma unroll
                for (int ni = 0; ni < 8; ni++)
                    mma_f16_f32(acc[mi][ni][0], acc[mi][ni][1], acc[mi][ni][2], acc[mi][ni][3],
                                a[mi][0], a[mi][1], a[mi][2], a[mi][3],
                                b[ni][0], b[ni][1]);
        }

        // ---- per-warp staged epilogue (dedicated buffer, no CTA barrier):
        //      out = xs[m] + ps[n] - 18*dot ----
        {
            const int n0 = (g & 127) << 7;
            const int m0 = (g >> 7) << 7;
            const int c_col0 = n0 + warp_n * 64;
            const int c_base = c_col0 + (lane & 3) * 2;
            float2 ps_[8];
            #pragma unroll
            for (int ni = 0; ni < 8; ni++)
                ps_[ni] = *reinterpret_cast<const float2*>(g_ps + c_base + ni * 8);

            #pragma unroll
            for (int mi = 0; mi < 4; mi++) {
                int r_base = m0 + warp_m * 64 + mi * 16;
                float xs0 = g_xs[r_base + row0];
                float xs1 = g_xs[r_base + 8 + row0];

                #pragma unroll
                for (int ni = 0; ni < 8; ni++) {
                    uint32_t chunk = (uint32_t)(ni ^ row0) << 5;
                    sts_v2(stg + row0 * 256 + chunk + ib,
                           xs0 + ps_[ni].x - 18.0f * acc[mi][ni][0],
                           xs0 + ps_[ni].y - 18.0f * acc[mi][ni][1]);
                    sts_v2(stg + (row0 + 8) * 256 + chunk + ib,
                           xs1 + ps_[ni].x - 18.0f * acc[mi][ni][2],
                           xs1 + ps_[ni].y - 18.0f * acc[mi][ni][3]);
                }
                __syncwarp();

                #pragma unroll
                for (int i = 0; i < 8; i++) {
                    int pos = i * 512 + lane * 16;
                    int rl  = pos >> 8;              // 0..15
                    int bib = pos & 255;
                    int ch  = bib >> 5;
                    uint32_t sa = stg + rl * 256 + ((uint32_t)(ch ^ (rl & 7)) << 5) + (bib & 31);
                    float x, y, z, w;
                    lds_v4(sa, x, y, z, w);
                    float* gp = out + (size_t)(r_base + rl) * C_ROWS + c_col0 + (bib >> 2);
                    stg_cs_v4(gp, x, y, z, w);
                }
                __syncwarp();
            }
        }

        // ---- A reload on m-row crossing (rare) ----
        if (has_next && next_m != (g >> 7)) {
            __syncthreads();
            load_tile_async(sb + SMEM_A_OFF, g_x + (size_t)(next_m << 7) * D_DIM, tid);
            asm volatile("cp.async.commit_group;");
        }

        cur ^= 1;
    }
}

// ============================================================================
extern "C" void kernel_launch(void* const* d_in, const int* in_sizes, int n_in,
                              void* d_out, int out_size) {
    (void)in_sizes; (void)n_in; (void)out_size;
    const float* inp = (const float*)d_in[0];   // inputs [4096,128] fp32
    const float* ker = (const float*)d_in[1];   // kernel [16384,128] fp32
    float* out = (float*)d_out;                 // [4096,16384] fp32

    cudaFuncSetAttribute(gemm_kernel, cudaFuncAttributeMaxDynamicSharedMemorySize, SMEM_TOTAL);

    int total_rows = B_ROWS + C_ROWS;            // 8 lanes per row
    int nthreads = total_rows * 8;
    normalize_kernel<<<(nthreads + 255) / 256, 256>>>(inp, ker);

    gemm_kernel<<<GRID, 128, SMEM_TOTAL>>>(out);
}

// round 14
// speedup vs baseline: 1.1484x; 1.0322x over previous
#include <cuda_runtime.h>
#include <cuda_fp16.h>
#include <cstdint>

// ============================================================================
// out[b,c] = xs[b] + ps[c] - 2 * dot(x_b, p_c)
//   x = 3*l2norm(inputs) [4096,128], p = 3*l2norm(kernel) [16384,128]
// R14: revert R13 grid barrier (deadlocked -> co-residency not guaranteed in
//      this environment). R12 structure, retuned for GB300's 152 SMs:
//      GRID=304 (2 CTAs/SM on 152 SMs), chunk sizes paired 14/13 so per-SM
//      tile sums drop 28 -> 27. Gemm: 4 warps @64x64, persistent, B double-
//      buffer, per-warp staged epilogue, f16 unit-norm inputs + f32 accum.
// ============================================================================

static constexpr int B_ROWS = 4096;
static constexpr int C_ROWS = 16384;
static constexpr int D_DIM  = 128;

static constexpr int N_TILES   = C_ROWS / 128;        // 128
static constexpr int M_TILES   = B_ROWS / 128;        // 32
static constexpr int TOT_TILES = N_TILES * M_TILES;   // 4096

static constexpr int GRID = 304;                      // 2 CTAs/SM on 152 SMs
static constexpr int BIG_CHUNKS = 144;                // 144*14 + 160*13 = 4096

static constexpr int SMEM_A_OFF  = 0;
static constexpr int TILE_BYTES  = 128 * 256;         // 32768 (f16 tile)
static constexpr int SMEM_B0_OFF = TILE_BYTES;        // 32768
static constexpr int SMEM_B1_OFF = 2 * TILE_BYTES;    // 65536
static constexpr int SMEM_STG_OFF = 3 * TILE_BYTES;   // 98304 (16KB staging)
static constexpr int SMEM_TOTAL  = SMEM_STG_OFF + 16384;  // 114688

// ---------------- scratch (no allocation allowed) ----------------
__device__ __half g_x[B_ROWS * D_DIM];   // unit-normalized rows
__device__ __half g_p[C_ROWS * D_DIM];
__device__ float g_xs[B_ROWS];           // ||3*norm(row)||^2
__device__ float g_ps[C_ROWS];

__device__ __forceinline__ uint32_t smem_u32(const void* p) {
    uint32_t a;
    asm("{ .reg .u64 t; cvta.to.shared.u64 t, %1; cvt.u32.u64 %0, t; }" : "=r"(a) : "l"(p));
    return a;
}
__device__ __forceinline__ void cp_async16(uint32_t dst, const void* src) {
    asm volatile("cp.async.cg.shared.global [%0], [%1], 16;" :: "r"(dst), "l"(src));
}
__device__ __forceinline__ void ldmatrix_x4(uint32_t& r0, uint32_t& r1,
                                            uint32_t& r2, uint32_t& r3, uint32_t addr) {
    asm volatile("ldmatrix.sync.aligned.m8n8.x4.shared.b16 {%0,%1,%2,%3}, [%4];"
                 : "=r"(r0), "=r"(r1), "=r"(r2), "=r"(r3) : "r"(addr));
}
__device__ __forceinline__ void mma_f16_f32(float& c0, float& c1, float& c2, float& c3,
                                            uint32_t a0, uint32_t a1, uint32_t a2, uint32_t a3,
                                            uint32_t b0, uint32_t b1) {
    asm volatile(
        "mma.sync.aligned.m16n8k16.row.col.f32.f16.f16.f32 "
        "{%0,%1,%2,%3}, {%4,%5,%6,%7}, {%8,%9}, {%0,%1,%2,%3};"
        : "+f"(c0), "+f"(c1), "+f"(c2), "+f"(c3)
        : "r"(a0), "r"(a1), "r"(a2), "r"(a3), "r"(b0), "r"(b1));
}
__device__ __forceinline__ void sts_v2(uint32_t addr, float x, float y) {
    asm volatile("st.shared.v2.f32 [%0], {%1,%2};" :: "r"(addr), "f"(x), "f"(y));
}
__device__ __forceinline__ void lds_v4(uint32_t addr, float& x, float& y, float& z, float& w) {
    asm volatile("ld.shared.v4.f32 {%0,%1,%2,%3}, [%4];"
                 : "=f"(x), "=f"(y), "=f"(z), "=f"(w) : "r"(addr));
}
__device__ __forceinline__ void stg_cs_v4(float* p, float x, float y, float z, float w) {
    asm volatile("st.global.cs.v4.f32 [%0], {%1,%2,%3,%4};"
                 :: "l"(p), "f"(x), "f"(y), "f"(z), "f"(w) : "memory");
}

// ============================================================================
// Kernel 1: normalize (unit scale) -> f16; xs/ps = 9*sum(u^2).
// 8 lanes per row; each lane holds 4 consecutive float4 (MLP=4/lane).
// ============================================================================
__global__ __launch_bounds__(256)
void normalize_kernel(const float* __restrict__ inp, const float* __restrict__ ker) {
    int gthread = blockIdx.x * blockDim.x + threadIdx.x;
    int row = gthread >> 3;
    int j   = gthread & 7;
    if (row >= B_ROWS + C_ROWS) return;

    const float* src;
    __half* outv;
    float* outs;
    int r;
    if (row < B_ROWS) { src = inp; outv = g_x; outs = g_xs; r = row; }
    else { src = ker; outv = g_p; outs = g_ps; r = row - B_ROWS; }

    const float4* s4 = reinterpret_cast<const float4*>(src + (size_t)r * D_DIM) + j * 4;
    float4 v0 = s4[0];
    float4 v1 = s4[1];
    float4 v2 = s4[2];
    float4 v3 = s4[3];

    float ss = v0.x * v0.x + v0.y * v0.y + v0.z * v0.z + v0.w * v0.w
             + v1.x * v1.x + v1.y * v1.y + v1.z * v1.z + v1.w * v1.w
             + v2.x * v2.x + v2.y * v2.y + v2.z * v2.z + v2.w * v2.w
             + v3.x * v3.x + v3.y * v3.y + v3.z * v3.z + v3.w * v3.w;
    #pragma unroll
    for (int o = 4; o; o >>= 1) ss += __shfl_xor_sync(0xffffffffu, ss, o);

    float rs = rsqrtf(fmaxf(ss, 1e-12f));       // unit scale
    __half2 h0 = __floats2half2_rn(v0.x * rs, v0.y * rs);
    __half2 h1 = __floats2half2_rn(v0.z * rs, v0.w * rs);
    __half2 h2 = __floats2half2_rn(v1.x * rs, v1.y * rs);
    __half2 h3 = __floats2half2_rn(v1.z * rs, v1.w * rs);
    __half2 h4 = __floats2half2_rn(v2.x * rs, v2.y * rs);
    __half2 h5 = __floats2half2_rn(v2.z * rs, v2.w * rs);
    __half2 h6 = __floats2half2_rn(v3.x * rs, v3.y * rs);
    __half2 h7 = __floats2half2_rn(v3.z * rs, v3.w * rs);
    uint4 pka, pkb;
    pka.x = *reinterpret_cast<uint32_t*>(&h0);
    pka.y = *reinterpret_cast<uint32_t*>(&h1);
    pka.z = *reinterpret_cast<uint32_t*>(&h2);
    pka.w = *reinterpret_cast<uint32_t*>(&h3);
    pkb.x = *reinterpret_cast<uint32_t*>(&h4);
    pkb.y = *reinterpret_cast<uint32_t*>(&h5);
    pkb.z = *reinterpret_cast<uint32_t*>(&h6);
    pkb.w = *reinterpret_cast<uint32_t*>(&h7);
    uint4* d4 = reinterpret_cast<uint4*>(outv + (size_t)r * D_DIM) + j * 2;
    d4[0] = pka;
    d4[1] = pkb;

    if (j == 0) outs[r] = 9.0f * ss * rs * rs;  // sum((3u)^2)
}

// async-load one 128x128 f16 tile (row-major 256B rows) into swizzled smem
__device__ __forceinline__ void load_tile_async(uint32_t smem_dst, const __half* gsrc,
                                                int tid) {
    const char* src = reinterpret_cast<const char*>(gsrc);
    #pragma unroll
    for (int it = 0; it < 16; it++) {
        int i = it * 128 + tid;
        int row = i >> 4, c = i & 15;
        uint32_t doff = row * 256 + ((c ^ (row & 7)) << 4);
        cp_async16(smem_dst + doff, src + (size_t)row * 256 + c * 16);
    }
}

// ============================================================================
// Kernel 2: persistent f16->f32 HMMA GEMM; 4 warps @ 64x64; per-warp staged
// epilogue in a dedicated buffer (no CTA barrier between compute & epilogue).
// SMEM tiles: 256B rows = 16 chunks of 16B; chunk c of row r at (c ^ (r&7)).
// ============================================================================
__global__ __launch_bounds__(128, 2)
void gemm_kernel(float* __restrict__ out) {
    extern __shared__ char smem[];
    const uint32_t sb = smem_u32(smem);

    const int tid  = threadIdx.x;
    const int lane = tid & 31;
    const int wid  = tid >> 5;
    const int warp_m = wid & 1;
    const int warp_n = wid >> 1;

    // chunk sizes: bids [0,144) -> 14 tiles, [144,304) -> 13 tiles.
    // bid s and s+152 land on the same SM (round-robin) -> per-SM sums 27/26.
    const int bid = blockIdx.x;
    int g0, g1;
    if (bid < BIG_CHUNKS) { g0 = bid * 14;                          g1 = g0 + 14; }
    else                  { g0 = BIG_CHUNKS * 14 + (bid - BIG_CHUNKS) * 13; g1 = g0 + 13; }

    // n-major tile order: g -> (m_tile = g>>7, n_tile = g&127)
    load_tile_async(sb + SMEM_A_OFF, g_x + (size_t)((g0 >> 7) << 7) * D_DIM, tid);
    load_tile_async(sb + SMEM_B0_OFF, g_p + (size_t)((g0 & 127) << 7) * D_DIM, tid);
    asm volatile("cp.async.commit_group;");

    const int a_row_base = warp_m * 64 + (lane & 7) + ((lane >> 3) & 1) * 8;
    const int a_kc_lane  = (lane >> 4);
    const int b_row_base = warp_n * 64 + (lane & 7) + (lane >> 4) * 8;
    const int b_kc_lane  = ((lane >> 3) & 1);

    const uint32_t stg = sb + SMEM_STG_OFF + wid * 4096;  // dedicated 4KB/warp
    const int row0 = lane >> 2;              // 0..7
    const int ib   = (lane & 3) << 3;

    int cur = 0;
    for (int g = g0; g < g1; g++) {
        asm volatile("cp.async.wait_group 0;" ::: "memory");
        __syncthreads();

        const bool has_next = (g + 1 < g1);
        const int  next_m   = (g + 1) >> 7;

        if (has_next) {
            load_tile_async(sb + (cur ? SMEM_B0_OFF : SMEM_B1_OFF),
                            g_p + (size_t)(((g + 1) & 127) << 7) * D_DIM, tid);
            asm volatile("cp.async.commit_group;");
        }

        // ---- compute 128x128 tile ----
        float acc[4][8][4];
        #pragma unroll
        for (int mi = 0; mi < 4; mi++)
            #pragma unroll
            for (int ni = 0; ni < 8; ni++)
                #pragma unroll
                for (int k = 0; k < 4; k++) acc[mi][ni][k] = 0.0f;

        const uint32_t sbB = sb + (cur ? SMEM_B1_OFF : SMEM_B0_OFF);

        #pragma unroll
        for (int ks = 0; ks < 8; ks++) {
            uint32_t a[4][4];
            #pragma unroll
            for (int mi = 0; mi < 4; mi++) {
                int row = a_row_base + mi * 16;
                int kc  = ks * 2 + a_kc_lane;
                uint32_t addr = sb + SMEM_A_OFF + row * 256 + ((kc ^ (row & 7)) << 4);
                ldmatrix_x4(a[mi][0], a[mi][1], a[mi][2], a[mi][3], addr);
            }
            uint32_t b[8][2];
            #pragma unroll
            for (int gg = 0; gg < 4; gg++) {
                int row = b_row_base + gg * 16;
                int kc  = ks * 2 + b_kc_lane;
                uint32_t addr = sbB + row * 256 + ((kc ^ (row & 7)) << 4);
                ldmatrix_x4(b[2 * gg][0], b[2 * gg][1], b[2 * gg + 1][0], b[2 * gg + 1][1], addr);
            }
            #pragma unroll
            for (int mi = 0; mi < 4; mi++)
                #pragma unroll
                for (int ni = 0; ni < 8; ni++)
                    mma_f16_f32(acc[mi][ni][0], acc[mi][ni][1], acc[mi][ni][2], acc[mi][ni][3],
                                a[mi][0], a[mi][1], a[mi][2], a[mi][3],
                                b[ni][0], b[ni][1]);
        }

        // ---- per-warp staged epilogue: out = xs[m] + ps[n] - 18*dot ----
        {
            const int n0 = (g & 127) << 7;
            const int m0 = (g >> 7) << 7;
            const int c_col0 = n0 + warp_n * 64;
            const int c_base = c_col0 + (lane & 3) * 2;
            float2 ps_[8];
            #pragma unroll
            for (int ni = 0; ni < 8; ni++)
                ps_[ni] = *reinterpret_cast<const float2*>(g_ps + c_base + ni * 8);

            #pragma unroll
            for (int mi = 0; mi < 4; mi++) {
                int r_base = m0 + warp_m * 64 + mi * 16;
                float xs0 = g_xs[r_base + row0];
                float xs1 = g_xs[r_base + 8 + row0];

                #pragma unroll
                for (int ni = 0; ni < 8; ni++) {
                    uint32_t chunk = (uint32_t)(ni ^ row0) << 5;
                    sts_v2(stg + row0 * 256 + chunk + ib,
                           xs0 + ps_[ni].x - 18.0f * acc[mi][ni][0],
                           xs0 + ps_[ni].y - 18.0f * acc[mi][ni][1]);
                    sts_v2(stg + (row0 + 8) * 256 + chunk + ib,
                           xs1 + ps_[ni].x - 18.0f * acc[mi][ni][2],
                           xs1 + ps_[ni].y - 18.0f * acc[mi][ni][3]);
                }
                __syncwarp();

                #pragma unroll
                for (int i = 0; i < 8; i++) {
                    int pos = i * 512 + lane * 16;
                    int rl  = pos >> 8;              // 0..15
                    int bib = pos & 255;
                    int ch  = bib >> 5;
                    uint32_t sa = stg + rl * 256 + ((uint32_t)(ch ^ (rl & 7)) << 5) + (bib & 31);
                    float x, y, z, w;
                    lds_v4(sa, x, y, z, w);
                    float* gp = out + (size_t)(r_base + rl) * C_ROWS + c_col0 + (bib >> 2);
                    stg_cs_v4(gp, x, y, z, w);
                }
                __syncwarp();
            }
        }

        // ---- A reload on m-row crossing (rare) ----
        if (has_next && next_m != (g >> 7)) {
            __syncthreads();
            load_tile_async(sb + SMEM_A_OFF, g_x + (size_t)(next_m << 7) * D_DIM, tid);
            asm volatile("cp.async.commit_group;");
        }

        cur ^= 1;
    }
}

// ============================================================================
extern "C" void kernel_launch(void* const* d_in, const int* in_sizes, int n_in,
                              void* d_out, int out_size) {
    (void)in_sizes; (void)n_in; (void)out_size;
    const float* inp = (const float*)d_in[0];   // inputs [4096,128] fp32
    const float* ker = (const float*)d_in[1];   // kernel [16384,128] fp32
    float* out = (float*)d_out;                 // [4096,16384] fp32

    cudaFuncSetAttribute(gemm_kernel, cudaFuncAttributeMaxDynamicSharedMemorySize, SMEM_TOTAL);

    int total_rows = B_ROWS + C_ROWS;            // 8 lanes per row
    int nthreads = total_rows * 8;
    normalize_kernel<<<(nthreads + 255) / 256, 256>>>(inp, ker);

    gemm_kernel<<<GRID, 128, SMEM_TOTAL>>>(out);
}

// round 15
// speedup vs baseline: 1.1748x; 1.0230x over previous
#include <cuda_runtime.h>
#include <cuda_fp16.h>
#include <cstdint>

// ============================================================================
// out[b,c] = xs[b] + ps[c] - 2 * dot(x_b, p_c)
//   x = 3*l2norm(inputs) [4096,128], p = 3*l2norm(kernel) [16384,128]
// R15: R14 (best: GRID=304 on 152 SMs, paired 14/13 chunks, 4 warps @64x64,
//      persistent, B double-buffer, per-warp staged epilogue, f16 unit-norm
//      + f32 accum) + PDL: gemm launched with ProgrammaticStreamSerialization
//      and gated by cudaGridDependencySynchronize() so its launch/prologue
//      overlaps the normalize kernel's tail.
// ============================================================================

static constexpr int B_ROWS = 4096;
static constexpr int C_ROWS = 16384;
static constexpr int D_DIM  = 128;

static constexpr int N_TILES   = C_ROWS / 128;        // 128
static constexpr int M_TILES   = B_ROWS / 128;        // 32
static constexpr int TOT_TILES = N_TILES * M_TILES;   // 4096

static constexpr int GRID = 304;                      // 2 CTAs/SM on 152 SMs
static constexpr int BIG_CHUNKS = 144;                // 144*14 + 160*13 = 4096

static constexpr int SMEM_A_OFF  = 0;
static constexpr int TILE_BYTES  = 128 * 256;         // 32768 (f16 tile)
static constexpr int SMEM_B0_OFF = TILE_BYTES;        // 32768
static constexpr int SMEM_B1_OFF = 2 * TILE_BYTES;    // 65536
static constexpr int SMEM_STG_OFF = 3 * TILE_BYTES;   // 98304 (16KB staging)
static constexpr int SMEM_TOTAL  = SMEM_STG_OFF + 16384;  // 114688

// ---------------- scratch (no allocation allowed) ----------------
__device__ __half g_x[B_ROWS * D_DIM];   // unit-normalized rows
__device__ __half g_p[C_ROWS * D_DIM];
__device__ float g_xs[B_ROWS];           // ||3*norm(row)||^2
__device__ float g_ps[C_ROWS];

__device__ __forceinline__ uint32_t smem_u32(const void* p) {
    uint32_t a;
    asm("{ .reg .u64 t; cvta.to.shared.u64 t, %1; cvt.u32.u64 %0, t; }" : "=r"(a) : "l"(p));
    return a;
}
__device__ __forceinline__ void cp_async16(uint32_t dst, const void* src) {
    asm volatile("cp.async.cg.shared.global [%0], [%1], 16;" :: "r"(dst), "l"(src));
}
__device__ __forceinline__ void ldmatrix_x4(uint32_t& r0, uint32_t& r1,
                                            uint32_t& r2, uint32_t& r3, uint32_t addr) {
    asm volatile("ldmatrix.sync.aligned.m8n8.x4.shared.b16 {%0,%1,%2,%3}, [%4];"
                 : "=r"(r0), "=r"(r1), "=r"(r2), "=r"(r3) : "r"(addr));
}
__device__ __forceinline__ void mma_f16_f32(float& c0, float& c1, float& c2, float& c3,
                                            uint32_t a0, uint32_t a1, uint32_t a2, uint32_t a3,
                                            uint32_t b0, uint32_t b1) {
    asm volatile(
        "mma.sync.aligned.m16n8k16.row.col.f32.f16.f16.f32 "
        "{%0,%1,%2,%3}, {%4,%5,%6,%7}, {%8,%9}, {%0,%1,%2,%3};"
        : "+f"(c0), "+f"(c1), "+f"(c2), "+f"(c3)
        : "r"(a0), "r"(a1), "r"(a2), "r"(a3), "r"(b0), "r"(b1));
}
__device__ __forceinline__ void sts_v2(uint32_t addr, float x, float y) {
    asm volatile("st.shared.v2.f32 [%0], {%1,%2};" :: "r"(addr), "f"(x), "f"(y));
}
__device__ __forceinline__ void lds_v4(uint32_t addr, float& x, float& y, float& z, float& w) {
    asm volatile("ld.shared.v4.f32 {%0,%1,%2,%3}, [%4];"
                 : "=f"(x), "=f"(y), "=f"(z), "=f"(w) : "r"(addr));
}
__device__ __forceinline__ void stg_cs_v4(float* p, float x, float y, float z, float w) {
    asm volatile("st.global.cs.v4.f32 [%0], {%1,%2,%3,%4};"
                 :: "l"(p), "f"(x), "f"(y), "f"(z), "f"(w) : "memory");
}

// ============================================================================
// Kernel 1: normalize (unit scale) -> f16; xs/ps = 9*sum(u^2).
// 8 lanes per row; each lane holds 4 consecutive float4 (MLP=4/lane).
// ============================================================================
__global__ __launch_bounds__(256)
void normalize_kernel(const float* __restrict__ inp, const float* __restrict__ ker) {
    int gthread = blockIdx.x * blockDim.x + threadIdx.x;
    int row = gthread >> 3;
    int j   = gthread & 7;
    if (row >= B_ROWS + C_ROWS) return;

    const float* src;
    __half* outv;
    float* outs;
    int r;
    if (row < B_ROWS) { src = inp; outv = g_x; outs = g_xs; r = row; }
    else { src = ker; outv = g_p; outs = g_ps; r = row - B_ROWS; }

    const float4* s4 = reinterpret_cast<const float4*>(src + (size_t)r * D_DIM) + j * 4;
    float4 v0 = s4[0];
    float4 v1 = s4[1];
    float4 v2 = s4[2];
    float4 v3 = s4[3];

    float ss = v0.x * v0.x + v0.y * v0.y + v0.z * v0.z + v0.w * v0.w
             + v1.x * v1.x + v1.y * v1.y + v1.z * v1.z + v1.w * v1.w
             + v2.x * v2.x + v2.y * v2.y + v2.z * v2.z + v2.w * v2.w
             + v3.x * v3.x + v3.y * v3.y + v3.z * v3.z + v3.w * v3.w;
    #pragma unroll
    for (int o = 4; o; o >>= 1) ss += __shfl_xor_sync(0xffffffffu, ss, o);

    float rs = rsqrtf(fmaxf(ss, 1e-12f));       // unit scale
    __half2 h0 = __floats2half2_rn(v0.x * rs, v0.y * rs);
    __half2 h1 = __floats2half2_rn(v0.z * rs, v0.w * rs);
    __half2 h2 = __floats2half2_rn(v1.x * rs, v1.y * rs);
    __half2 h3 = __floats2half2_rn(v1.z * rs, v1.w * rs);
    __half2 h4 = __floats2half2_rn(v2.x * rs, v2.y * rs);
    __half2 h5 = __floats2half2_rn(v2.z * rs, v2.w * rs);
    __half2 h6 = __floats2half2_rn(v3.x * rs, v3.y * rs);
    __half2 h7 = __floats2half2_rn(v3.z * rs, v3.w * rs);
    uint4 pka, pkb;
    pka.x = *reinterpret_cast<uint32_t*>(&h0);
    pka.y = *reinterpret_cast<uint32_t*>(&h1);
    pka.z = *reinterpret_cast<uint32_t*>(&h2);
    pka.w = *reinterpret_cast<uint32_t*>(&h3);
    pkb.x = *reinterpret_cast<uint32_t*>(&h4);
    pkb.y = *reinterpret_cast<uint32_t*>(&h5);
    pkb.z = *reinterpret_cast<uint32_t*>(&h6);
    pkb.w = *reinterpret_cast<uint32_t*>(&h7);
    uint4* d4 = reinterpret_cast<uint4*>(outv + (size_t)r * D_DIM) + j * 2;
    d4[0] = pka;
    d4[1] = pkb;

    if (j == 0) outs[r] = 9.0f * ss * rs * rs;  // sum((3u)^2)
}

// async-load one 128x128 f16 tile (row-major 256B rows) into swizzled smem
__device__ __forceinline__ void load_tile_async(uint32_t smem_dst, const __half* gsrc,
                                                int tid) {
    const char* src = reinterpret_cast<const char*>(gsrc);
    #pragma unroll
    for (int it = 0; it < 16; it++) {
        int i = it * 128 + tid;
        int row = i >> 4, c = i & 15;
        uint32_t doff = row * 256 + ((c ^ (row & 7)) << 4);
        cp_async16(smem_dst + doff, src + (size_t)row * 256 + c * 16);
    }
}

// ============================================================================
// Kernel 2: persistent f16->f32 HMMA GEMM; 4 warps @ 64x64; per-warp staged
// epilogue. PDL-gated: launch overlaps normalize, griddepcontrol.wait before
// the first dependent global read.
// ============================================================================
__global__ __launch_bounds__(128, 2)
void gemm_kernel(float* __restrict__ out) {
    extern __shared__ char smem[];
    const uint32_t sb = smem_u32(smem);

    const int tid  = threadIdx.x;
    const int lane = tid & 31;
    const int wid  = tid >> 5;
    const int warp_m = wid & 1;
    const int warp_n = wid >> 1;

    // chunk sizes: bids [0,144) -> 14 tiles, [144,304) -> 13 tiles.
    // bid s and s+152 land on the same SM (round-robin) -> per-SM sums 27/26.
    const int bid = blockIdx.x;
    int g0, g1;
    if (bid < BIG_CHUNKS) { g0 = bid * 14;                          g1 = g0 + 14; }
    else                  { g0 = BIG_CHUNKS * 14 + (bid - BIG_CHUNKS) * 13; g1 = g0 + 13; }

    const int a_row_base = warp_m * 64 + (lane & 7) + ((lane >> 3) & 1) * 8;
    const int a_kc_lane  = (lane >> 4);
    const int b_row_base = warp_n * 64 + (lane & 7) + (lane >> 4) * 8;
    const int b_kc_lane  = ((lane >> 3) & 1);

    const uint32_t stg = sb + SMEM_STG_OFF + wid * 4096;  // dedicated 4KB/warp
    const int row0 = lane >> 2;              // 0..7
    const int ib   = (lane & 3) << 3;

    // PDL gate: wait for the normalize kernel's writes to be visible.
    cudaGridDependencySynchronize();

    // n-major tile order: g -> (m_tile = g>>7, n_tile = g&127)
    load_tile_async(sb + SMEM_A_OFF, g_x + (size_t)((g0 >> 7) << 7) * D_DIM, tid);
    load_tile_async(sb + SMEM_B0_OFF, g_p + (size_t)((g0 & 127) << 7) * D_DIM, tid);
    asm volatile("cp.async.commit_group;");

    int cur = 0;
    for (int g = g0; g < g1; g++) {
        asm volatile("cp.async.wait_group 0;" ::: "memory");
        __syncthreads();

        const bool has_next = (g + 1 < g1);
        const int  next_m   = (g + 1) >> 7;

        if (has_next) {
            load_tile_async(sb + (cur ? SMEM_B0_OFF : SMEM_B1_OFF),
                            g_p + (size_t)(((g + 1) & 127) << 7) * D_DIM, tid);
            asm volatile("cp.async.commit_group;");
        }

        // ---- compute 128x128 tile ----
        float acc[4][8][4];
        #pragma unroll
        for (int mi = 0; mi < 4; mi++)
            #pragma unroll
            for (int ni = 0; ni < 8; ni++)
                #pragma unroll
                for (int k = 0; k < 4; k++) acc[mi][ni][k] = 0.0f;

        const uint32_t sbB = sb + (cur ? SMEM_B1_OFF : SMEM_B0_OFF);

        #pragma unroll
        for (int ks = 0; ks < 8; ks++) {
            uint32_t a[4][4];
            #pragma unroll
            for (int mi = 0; mi < 4; mi++) {
                int row = a_row_base + mi * 16;
                int kc  = ks * 2 + a_kc_lane;
                uint32_t addr = sb + SMEM_A_OFF + row * 256 + ((kc ^ (row & 7)) << 4);
                ldmatrix_x4(a[mi][0], a[mi][1], a[mi][2], a[mi][3], addr);
            }
            uint32_t b[8][2];
            #pragma unroll
            for (int gg = 0; gg < 4; gg++) {
                int row = b_row_base + gg * 16;
                int kc  = ks * 2 + b_kc_lane;
                uint32_t addr = sbB + row * 256 + ((kc ^ (row & 7)) << 4);
                ldmatrix_x4(b[2 * gg][0], b[2 * gg][1], b[2 * gg + 1][0], b[2 * gg + 1][1], addr);
            }
            #pragma unroll
            for (int mi = 0; mi < 4; mi++)
                #pragma unroll
                for (int ni = 0; ni < 8; ni++)
                    mma_f16_f32(acc[mi][ni][0], acc[mi][ni][1], acc[mi][ni][2], acc[mi][ni][3],
                                a[mi][0], a[mi][1], a[mi][2], a[mi][3],
                                b[ni][0], b[ni][1]);
        }

        // ---- per-warp staged epilogue: out = xs[m] + ps[n] - 18*dot ----
        {
            const int n0 = (g & 127) << 7;
            const int m0 = (g >> 7) << 7;
            const int c_col0 = n0 + warp_n * 64;
            const int c_base = c_col0 + (lane & 3) * 2;
            float2 ps_[8];
            #pragma unroll
            for (int ni = 0; ni < 8; ni++)
                ps_[ni] = *reinterpret_cast<const float2*>(g_ps + c_base + ni * 8);

            #pragma unroll
            for (int mi = 0; mi < 4; mi++) {
                int r_base = m0 + warp_m * 64 + mi * 16;
                float xs0 = g_xs[r_base + row0];
                float xs1 = g_xs[r_base + 8 + row0];

                #pragma unroll
                for (int ni = 0; ni < 8; ni++) {
                    uint32_t chunk = (uint32_t)(ni ^ row0) << 5;
                    sts_v2(stg + row0 * 256 + chunk + ib,
                           xs0 + ps_[ni].x - 18.0f * acc[mi][ni][0],
                           xs0 + ps_[ni].y - 18.0f * acc[mi][ni][1]);
                    sts_v2(stg + (row0 + 8) * 256 + chunk + ib,
                           xs1 + ps_[ni].x - 18.0f * acc[mi][ni][2],
                           xs1 + ps_[ni].y - 18.0f * acc[mi][ni][3]);
                }
                __syncwarp();

                #pragma unroll
                for (int i = 0; i < 8; i++) {
                    int pos = i * 512 + lane * 16;
                    int rl  = pos >> 8;              // 0..15
                    int bib = pos & 255;
                    int ch  = bib >> 5;
                    uint32_t sa = stg + rl * 256 + ((uint32_t)(ch ^ (rl & 7)) << 5) + (bib & 31);
                    float x, y, z, w;
                    lds_v4(sa, x, y, z, w);
                    float* gp = out + (size_t)(r_base + rl) * C_ROWS + c_col0 + (bib >> 2);
                    stg_cs_v4(gp, x, y, z, w);
                }
                __syncwarp();
            }
        }

        // ---- A reload on m-row crossing (rare) ----
        if (has_next && next_m != (g >> 7)) {
            __syncthreads();
            load_tile_async(sb + SMEM_A_OFF, g_x + (size_t)(next_m << 7) * D_DIM, tid);
            asm volatile("cp.async.commit_group;");
        }

        cur ^= 1;
    }
}

// ============================================================================
extern "C" void kernel_launch(void* const* d_in, const int* in_sizes, int n_in,
                              void* d_out, int out_size) {
    (void)in_sizes; (void)n_in; (void)out_size;
    const float* inp = (const float*)d_in[0];   // inputs [4096,128] fp32
    const float* ker = (const float*)d_in[1];   // kernel [16384,128] fp32
    float* out = (float*)d_out;                 // [4096,16384] fp32

    cudaFuncSetAttribute(gemm_kernel, cudaFuncAttributeMaxDynamicSharedMemorySize, SMEM_TOTAL);

    int total_rows = B_ROWS + C_ROWS;            // 8 lanes per row
    int nthreads = total_rows * 8;
    normalize_kernel<<<(nthreads + 255) / 256, 256>>>(inp, ker);

    // PDL launch: gemm spins up while normalize drains; griddepcontrol.wait
    // inside the kernel provides the data dependency.
    cudaLaunchConfig_t cfg = {};
    cfg.gridDim = dim3(GRID, 1, 1);
    cfg.blockDim = dim3(128, 1, 1);
    cfg.dynamicSmemBytes = SMEM_TOTAL;
    cfg.stream = 0;
    cudaLaunchAttribute attrs[1];
    attrs[0].id = cudaLaunchAttributeProgrammaticStreamSerialization;
    attrs[0].val.programmaticStreamSerializationAllowed = 1;
    cfg.attrs = attrs;
    cfg.numAttrs = 1;
    cudaLaunchKernelEx(&cfg, gemm_kernel, out);
}